// round 8
// baseline (speedup 1.0000x reference)
#include <cuda_runtime.h>
#include <cuda_bf16.h>
#include <cstdint>
#include <cstddef>

// Problem constants
#define Bg    16
#define Ntok  512
#define Eg    131072
#define MROWS (Bg * Ntok)          // 8192
#define SCALE 0.17677669529663687f // 1/sqrt(32)

// Scratch (device globals; no allocation allowed)
__device__ float    g_q[MROWS * 256];
__device__ float    g_k[MROWS * 256];
__device__ float    g_v[MROWS * 256];
__device__ unsigned g_mask[Bg * Ntok * 16];  // 131072 words
__device__ __align__(16) __nv_bfloat16 g_h_hi[MROWS * 256];
__device__ __align__(16) __nv_bfloat16 g_h_lo[MROWS * 256];
__device__ __align__(16) __nv_bfloat16 g_att_hi[MROWS * 256];
__device__ __align__(16) __nv_bfloat16 g_att_lo[MROWS * 256];
// Transposed + hi/lo-split weights: [4 weights][N=256 rows][K=256 cols] K-major
__device__ __align__(16) __nv_bfloat16 g_wt_hi[4 * 256 * 256];
__device__ __align__(16) __nv_bfloat16 g_wt_lo[4 * 256 * 256];

// ---------------------------------------------------------------------------
// Warp-MMA + cp.async helpers (portable sm_80+ path; harness PTX target is
// compute_100 without 'a' suffix -> tcgen05 unavailable)
// ---------------------------------------------------------------------------
__device__ __forceinline__ void ldsm_x4(uint32_t addr, uint32_t* r) {
    asm volatile("ldmatrix.sync.aligned.m8n8.x4.shared.b16 {%0,%1,%2,%3}, [%4];"
                 : "=r"(r[0]), "=r"(r[1]), "=r"(r[2]), "=r"(r[3]) : "r"(addr));
}
__device__ __forceinline__ void ldsm_x2(uint32_t addr, uint32_t* r) {
    asm volatile("ldmatrix.sync.aligned.m8n8.x2.shared.b16 {%0,%1}, [%2];"
                 : "=r"(r[0]), "=r"(r[1]) : "r"(addr));
}
__device__ __forceinline__ void mma_bf16(float* c, const uint32_t* a, const uint32_t* b) {
    asm volatile(
        "mma.sync.aligned.m16n8k16.row.col.f32.bf16.bf16.f32 "
        "{%0,%1,%2,%3}, {%4,%5,%6,%7}, {%8,%9}, {%0,%1,%2,%3};"
        : "+f"(c[0]), "+f"(c[1]), "+f"(c[2]), "+f"(c[3])
        : "r"(a[0]), "r"(a[1]), "r"(a[2]), "r"(a[3]), "r"(b[0]), "r"(b[1]));
}
__device__ __forceinline__ uint32_t pack_bf2(__nv_bfloat16 a, __nv_bfloat16 b) {
    __nv_bfloat162 t(a, b);
    return *reinterpret_cast<uint32_t*>(&t);
}
__device__ __forceinline__ void cp16(uint32_t dst, const void* src) {
    asm volatile("cp.async.cg.shared.global [%0], [%1], 16;" :: "r"(dst), "l"(src));
}
#define CP_COMMIT() asm volatile("cp.async.commit_group;")
#define CP_WAIT2()  asm volatile("cp.async.wait_group 2;")

// ---------------------------------------------------------------------------
// h -> bf16 hi/lo split (one float4 per thread)
// ---------------------------------------------------------------------------
__global__ void hsplit_kernel(const float* __restrict__ h,
                              __nv_bfloat16* __restrict__ hh,
                              __nv_bfloat16* __restrict__ hl) {
    int i = blockIdx.x * 256 + threadIdx.x;       // < 524288 float4s
    float4 v = reinterpret_cast<const float4*>(h)[i];
    __nv_bfloat16 h0 = __float2bfloat16(v.x), h1 = __float2bfloat16(v.y);
    __nv_bfloat16 h2 = __float2bfloat16(v.z), h3 = __float2bfloat16(v.w);
    __nv_bfloat16 l0 = __float2bfloat16(v.x - __bfloat162float(h0));
    __nv_bfloat16 l1 = __float2bfloat16(v.y - __bfloat162float(h1));
    __nv_bfloat16 l2 = __float2bfloat16(v.z - __bfloat162float(h2));
    __nv_bfloat16 l3 = __float2bfloat16(v.w - __bfloat162float(h3));
    uint2 uh, ul;
    uh.x = pack_bf2(h0, h1); uh.y = pack_bf2(h2, h3);
    ul.x = pack_bf2(l0, l1); ul.y = pack_bf2(l2, l3);
    reinterpret_cast<uint2*>(hh)[i] = uh;
    reinterpret_cast<uint2*>(hl)[i] = ul;
}

// ---------------------------------------------------------------------------
// Weight prep: W[K=256][N=256] fp32 -> Wt_hi/Wt_lo[N][K] bf16 (transpose+split)
// ---------------------------------------------------------------------------
__global__ void wsplit_kernel(const float* __restrict__ Wq, const float* __restrict__ Wk,
                              const float* __restrict__ Wv, const float* __restrict__ Wo,
                              __nv_bfloat16* __restrict__ wt_hi,
                              __nv_bfloat16* __restrict__ wt_lo) {
    const float* W = (blockIdx.z == 0) ? Wq : (blockIdx.z == 1) ? Wk
                   : (blockIdx.z == 2) ? Wv : Wo;
    __shared__ float tile[32][33];
    int tx = threadIdx.x, ty = threadIdx.y;
    int n0 = blockIdx.x * 32, k0 = blockIdx.y * 32;
#pragma unroll
    for (int j = 0; j < 4; j++)
        tile[ty + 8 * j][tx] = W[(k0 + ty + 8 * j) * 256 + n0 + tx];
    __syncthreads();
    size_t wbase = (size_t)blockIdx.z * 65536;
#pragma unroll
    for (int j = 0; j < 4; j++) {
        int n = n0 + ty + 8 * j;
        int k = k0 + tx;
        float x = tile[tx][ty + 8 * j];
        __nv_bfloat16 hi = __float2bfloat16(x);
        __nv_bfloat16 lo = __float2bfloat16(x - __bfloat162float(hi));
        wt_hi[wbase + (size_t)n * 256 + k] = hi;
        wt_lo[wbase + (size_t)n * 256 + k] = lo;
    }
}

// ---------------------------------------------------------------------------
// Mask build: diag (self loops) + edge scatter
// ---------------------------------------------------------------------------
__global__ void mask_init_kernel(unsigned* __restrict__ mask) {
    int idx = blockIdx.x * 256 + threadIdx.x;
    int w = idx & 15;
    int r = (idx >> 4) & 511;
    mask[idx] = ((r >> 5) == w) ? (1u << (r & 31)) : 0u;
}

__global__ void mask_edges_kernel(const int* __restrict__ src,
                                  const int* __restrict__ dst,
                                  unsigned* __restrict__ mask) {
    int i = blockIdx.x * 256 + threadIdx.x;
    int s = src[i];
    int d = dst[i];
    int b = s >> 9;
    int r = s & 511;
    int c = d & 511;
    atomicOr(&mask[((b << 9) + r) * 16 + (c >> 5)], 1u << (c & 31));
}

// ---------------------------------------------------------------------------
// bf16 hi/lo split GEMM, 4-stage cp.async pipeline.
// C[128,128] = A[128,256] @ Wt^T + bias per block. 3-term Markidis.
// 512 threads = 16 warps (4m x 4n), warp tile 32x32, m16n8k16 mma.sync.
// smem rows stride 80B -> ldmatrix/cp.async conflict-free.
// ---------------------------------------------------------------------------
#define KCH   32
#define NCHNK 8
#define ASTR  40                 // halfs per smem row (80 B)
#define AH_B  0
#define AL_B  10240
#define BH_B  20480
#define BL_B  30720
#define STG_B 40960
#define NSTG  4
#define SMEM_DYN (NSTG * STG_B)  // 163840

__device__ __forceinline__ void issue_stage(
    uint32_t stb,
    const __nv_bfloat16* __restrict__ ah, const __nv_bfloat16* __restrict__ al,
    const __nv_bfloat16* __restrict__ bh, const __nv_bfloat16* __restrict__ bl,
    int row0, int col0, int ch, int tid) {
    int r = tid >> 2, c = tid & 3;                 // r 0..127, c 0..3 (16B units)
    uint32_t doff = (uint32_t)(r * 80 + c * 16);
    size_t goff = (size_t)r * 256 + ch * KCH + c * 8;
    cp16(stb + AH_B + doff, ah + (size_t)row0 * 256 + goff);
    cp16(stb + AL_B + doff, al + (size_t)row0 * 256 + goff);
    cp16(stb + BH_B + doff, bh + (size_t)col0 * 256 + goff);
    cp16(stb + BL_B + doff, bl + (size_t)col0 * 256 + goff);
}

__device__ __forceinline__ void mma_gemm_body(
    const __nv_bfloat16* __restrict__ a_hi, const __nv_bfloat16* __restrict__ a_lo,
    const __nv_bfloat16* __restrict__ wth,  const __nv_bfloat16* __restrict__ wtl,
    const float* __restrict__ bias,
    float* __restrict__ C, int row0, int col0) {
    extern __shared__ __align__(16) char smem_dyn[];
    uint32_t sb = (uint32_t)__cvta_generic_to_shared(smem_dyn);

    int tid  = threadIdx.x;           // 0..511
    int wid  = tid >> 5;
    int lane = tid & 31;
    int wrow = (wid >> 2) * 32;
    int wn   = (wid & 3) * 32;

    int arow = wrow + (lane & 15);
    int ac8  = ((lane >> 4) & 1) * 8;
    int brow = wn + (lane & 7);
    int bc8  = ((lane >> 3) & 1) * 8;

    float acc[2][4][4];
#pragma unroll
    for (int mt = 0; mt < 2; mt++)
#pragma unroll
        for (int nt = 0; nt < 4; nt++)
#pragma unroll
            for (int i = 0; i < 4; i++) acc[mt][nt][i] = 0.f;

    // Prologue: stages 0..2
#pragma unroll
    for (int s = 0; s < NSTG - 1; s++) {
        issue_stage(sb + s * STG_B, a_hi, a_lo, wth, wtl, row0, col0, s, tid);
        CP_COMMIT();
    }

#pragma unroll 1
    for (int ch = 0; ch < NCHNK; ch++) {
        CP_WAIT2();
        __syncthreads();
        int nxt = ch + NSTG - 1;
        if (nxt < NCHNK) {
            issue_stage(sb + (nxt & (NSTG - 1)) * STG_B,
                        a_hi, a_lo, wth, wtl, row0, col0, nxt, tid);
            CP_COMMIT();
        }
        uint32_t stb = sb + (ch & (NSTG - 1)) * STG_B;

#pragma unroll
        for (int ks = 0; ks < 2; ks++) {
            uint32_t ah[2][4], al[2][4], bh[4][2], bl[4][2];
#pragma unroll
            for (int mt = 0; mt < 2; mt++) {
                uint32_t off = (uint32_t)(((arow + mt * 16) * ASTR + ks * 16 + ac8) * 2);
                ldsm_x4(stb + AH_B + off, ah[mt]);
                ldsm_x4(stb + AL_B + off, al[mt]);
            }
#pragma unroll
            for (int nt = 0; nt < 4; nt++) {
                uint32_t off = (uint32_t)(((brow + nt * 8) * ASTR + ks * 16 + bc8) * 2);
                ldsm_x2(stb + BH_B + off, bh[nt]);
                ldsm_x2(stb + BL_B + off, bl[nt]);
            }
#pragma unroll
            for (int mt = 0; mt < 2; mt++)
#pragma unroll
                for (int nt = 0; nt < 4; nt++) {
                    mma_bf16(acc[mt][nt], ah[mt], bh[nt]);
                    mma_bf16(acc[mt][nt], ah[mt], bl[nt]);
                    mma_bf16(acc[mt][nt], al[mt], bh[nt]);
                }
        }
    }

    // Epilogue
#pragma unroll
    for (int mt = 0; mt < 2; mt++) {
#pragma unroll
        for (int nt = 0; nt < 4; nt++) {
            int r = row0 + wrow + mt * 16 + (lane >> 2);
            int c = col0 + wn + nt * 8 + (lane & 3) * 2;
            float b0 = bias[c], b1 = bias[c + 1];
            float2 o0 = make_float2(acc[mt][nt][0] + b0, acc[mt][nt][1] + b1);
            float2 o1 = make_float2(acc[mt][nt][2] + b0, acc[mt][nt][3] + b1);
            *reinterpret_cast<float2*>(C + (size_t)r * 256 + c)       = o0;
            *reinterpret_cast<float2*>(C + (size_t)(r + 8) * 256 + c) = o1;
        }
    }
}

__global__ __launch_bounds__(512, 1) void mma_qkv_kernel(
    const __nv_bfloat16* __restrict__ a_hi, const __nv_bfloat16* __restrict__ a_lo,
    const __nv_bfloat16* __restrict__ wt_hi, const __nv_bfloat16* __restrict__ wt_lo,
    const float* bq, const float* bk, const float* bv,
    float* q, float* k, float* v) {
    int wsel = blockIdx.z;
    const float* bias = (wsel == 0) ? bq : (wsel == 1) ? bk : bv;
    float* C = (wsel == 0) ? q : (wsel == 1) ? k : v;
    mma_gemm_body(a_hi, a_lo, wt_hi + (size_t)wsel * 65536, wt_lo + (size_t)wsel * 65536,
                  bias, C, blockIdx.x * 128, blockIdx.y * 128);
}

__global__ __launch_bounds__(512, 1) void mma_o_kernel(
    const __nv_bfloat16* __restrict__ a_hi, const __nv_bfloat16* __restrict__ a_lo,
    const __nv_bfloat16* __restrict__ wt_hi, const __nv_bfloat16* __restrict__ wt_lo,
    const float* __restrict__ bias, float* __restrict__ C) {
    mma_gemm_body(a_hi, a_lo, wt_hi + (size_t)3 * 65536, wt_lo + (size_t)3 * 65536,
                  bias, C, blockIdx.x * 128, blockIdx.y * 128);
}

// ---------------------------------------------------------------------------
// Sparse masked attention, all 8 heads per warp; output written directly as
// bf16 hi/lo split (input for the O projection GEMM).
// ---------------------------------------------------------------------------
__global__ __launch_bounds__(256) void attn_kernel(
    const float* __restrict__ q, const float* __restrict__ k,
    const float* __restrict__ v, const unsigned* __restrict__ mask,
    __nv_bfloat16* __restrict__ att_hi, __nv_bfloat16* __restrict__ att_lo) {
    int gw   = blockIdx.x * 8 + (threadIdx.x >> 5);
    int lane = threadIdx.x & 31;
    int qi = gw & 511;
    int b  = gw >> 9;

    int off = lane * 8;
    size_t qrow = (size_t)gw * 256;
    float4 qa = *reinterpret_cast<const float4*>(q + qrow + off);
    float4 qb = *reinterpret_cast<const float4*>(q + qrow + off + 4);

    float m = -1e30f, l = 0.f;
    float acc[8];
#pragma unroll
    for (int d = 0; d < 8; d++) acc[d] = 0.f;

    const unsigned* mrow = mask + ((b << 9) + qi) * 16;
    size_t bbase = (size_t)(b << 9) * 256;

#pragma unroll 1
    for (int w = 0; w < 16; w++) {
        unsigned bits = mrow[w];
        while (bits) {
            int bit = __ffs(bits) - 1;
            bits &= bits - 1;
            int j = (w << 5) + bit;
            const float* krow = k + bbase + (size_t)j * 256 + off;
            const float* vrow = v + bbase + (size_t)j * 256 + off;
            float4 ka = *reinterpret_cast<const float4*>(krow);
            float4 kb = *reinterpret_cast<const float4*>(krow + 4);
            float4 va = *reinterpret_cast<const float4*>(vrow);
            float4 vb = *reinterpret_cast<const float4*>(vrow + 4);

            float s = qa.x * ka.x + qa.y * ka.y + qa.z * ka.z + qa.w * ka.w
                    + qb.x * kb.x + qb.y * kb.y + qb.z * kb.z + qb.w * kb.w;
            s += __shfl_xor_sync(0xffffffffu, s, 1);
            s += __shfl_xor_sync(0xffffffffu, s, 2);
            s *= SCALE;

            float mn   = fmaxf(m, s);
            float corr = __expf(m - mn);
            float p    = __expf(s - mn);
            l = l * corr + p;
            m = mn;
            acc[0] = acc[0] * corr + p * va.x;
            acc[1] = acc[1] * corr + p * va.y;
            acc[2] = acc[2] * corr + p * va.z;
            acc[3] = acc[3] * corr + p * va.w;
            acc[4] = acc[4] * corr + p * vb.x;
            acc[5] = acc[5] * corr + p * vb.y;
            acc[6] = acc[6] * corr + p * vb.z;
            acc[7] = acc[7] * corr + p * vb.w;
        }
    }

    float inv = 1.f / l;
    __nv_bfloat16 hi[8], lo[8];
#pragma unroll
    for (int d = 0; d < 8; d++) {
        float o = acc[d] * inv;
        hi[d] = __float2bfloat16(o);
        lo[d] = __float2bfloat16(o - __bfloat162float(hi[d]));
    }
    uint4 uh, ul;
    uh.x = pack_bf2(hi[0], hi[1]); uh.y = pack_bf2(hi[2], hi[3]);
    uh.z = pack_bf2(hi[4], hi[5]); uh.w = pack_bf2(hi[6], hi[7]);
    ul.x = pack_bf2(lo[0], lo[1]); ul.y = pack_bf2(lo[2], lo[3]);
    ul.z = pack_bf2(lo[4], lo[5]); ul.w = pack_bf2(lo[6], lo[7]);
    *reinterpret_cast<uint4*>(att_hi + qrow + off) = uh;
    *reinterpret_cast<uint4*>(att_lo + qrow + off) = ul;
}

// ---------------------------------------------------------------------------
// Launch
// ---------------------------------------------------------------------------
extern "C" void kernel_launch(void* const* d_in, const int* in_sizes, int n_in,
                              void* d_out, int out_size) {
    const float* h   = (const float*)d_in[0];
    const int*   src = (const int*)d_in[1];
    const int*   dst = (const int*)d_in[2];
    const float* Wq  = (const float*)d_in[3];
    const float* bq  = (const float*)d_in[4];
    const float* Wk  = (const float*)d_in[5];
    const float* bk  = (const float*)d_in[6];
    const float* Wv  = (const float*)d_in[7];
    const float* bv  = (const float*)d_in[8];
    const float* Wo  = (const float*)d_in[9];
    const float* bo  = (const float*)d_in[10];
    float* out = (float*)d_out;

    float *pq, *pk, *pv;
    unsigned* pmask;
    __nv_bfloat16 *pwh, *pwl, *phh, *phl, *pah, *pal;
    cudaGetSymbolAddress((void**)&pq,    g_q);
    cudaGetSymbolAddress((void**)&pk,    g_k);
    cudaGetSymbolAddress((void**)&pv,    g_v);
    cudaGetSymbolAddress((void**)&pmask, g_mask);
    cudaGetSymbolAddress((void**)&pwh,   g_wt_hi);
    cudaGetSymbolAddress((void**)&pwl,   g_wt_lo);
    cudaGetSymbolAddress((void**)&phh,   g_h_hi);
    cudaGetSymbolAddress((void**)&phl,   g_h_lo);
    cudaGetSymbolAddress((void**)&pah,   g_att_hi);
    cudaGetSymbolAddress((void**)&pal,   g_att_lo);

    cudaFuncSetAttribute(mma_qkv_kernel,
                         cudaFuncAttributeMaxDynamicSharedMemorySize, SMEM_DYN);
    cudaFuncSetAttribute(mma_o_kernel,
                         cudaFuncAttributeMaxDynamicSharedMemorySize, SMEM_DYN);

    // Prep: activation split, weight transpose+split, mask build
    hsplit_kernel<<<MROWS * 256 / 4 / 256, 256>>>(h, phh, phl);
    wsplit_kernel<<<dim3(8, 8, 4), dim3(32, 8)>>>(Wq, Wk, Wv, Wo, pwh, pwl);
    mask_init_kernel<<<Bg * Ntok * 16 / 256, 256>>>(pmask);
    mask_edges_kernel<<<Eg / 256, 256>>>(src, dst, pmask);

    // Q/K/V projections (cp.async pipelined bf16-split MMA)
    mma_qkv_kernel<<<dim3(MROWS / 128, 2, 3), 512, SMEM_DYN>>>(
        phh, phl, pwh, pwl, bq, bk, bv, pq, pk, pv);

    // Sparse masked attention -> bf16 hi/lo output
    attn_kernel<<<MROWS / 8, 256>>>(pq, pk, pv, pmask, pah, pal);

    // Output projection straight into d_out
    mma_o_kernel<<<dim3(MROWS / 128, 2), 512, SMEM_DYN>>>(pah, pal, pwh, pwl, bo, out);
}